// round 2
// baseline (speedup 1.0000x reference)
#include <cuda_runtime.h>
#include <math.h>

#define BATCH 4
#define SEQ   2048
#define DMODEL 512
#define NHEAD 8
#define DHEAD 64
#define MROWS (BATCH*SEQ)          // 8192
#define NEG_INF_F (-4294967295.0f) // -2^32+1
#define LN_EPS_F 1e-8f
#define SPAD 68                    // padded smem row stride

// ---- scratch (no allocs allowed) ----
__device__ float g_Q[MROWS*DMODEL];
__device__ float g_K[MROWS*DMODEL];
__device__ float g_V[MROWS*DMODEL];
__device__ float g_att[MROWS*DMODEL];
__device__ float g_qmask[MROWS];
__device__ float g_kmask[MROWS];

// ============================================================
// masks: sign(|sum_d x|) per row, for queries and keys
// ============================================================
__global__ void mask_kernel(const float* __restrict__ queries,
                            const float* __restrict__ keys) {
    int row = blockIdx.x;
    int tid = threadIdx.x; // 128
    const float* q = queries + (size_t)row * DMODEL;
    const float* k = keys    + (size_t)row * DMODEL;
    float sq = 0.f, sk = 0.f;
    for (int i = tid; i < DMODEL; i += 128) { sq += q[i]; sk += k[i]; }
    #pragma unroll
    for (int off = 16; off; off >>= 1) {
        sq += __shfl_xor_sync(0xffffffffu, sq, off);
        sk += __shfl_xor_sync(0xffffffffu, sk, off);
    }
    __shared__ float bq[4], bk[4];
    if ((tid & 31) == 0) { bq[tid >> 5] = sq; bk[tid >> 5] = sk; }
    __syncthreads();
    if (tid == 0) {
        float tq = bq[0] + bq[1] + bq[2] + bq[3];
        float tk = bk[0] + bk[1] + bk[2] + bk[3];
        g_qmask[row] = (tq != 0.f) ? 1.f : 0.f;
        g_kmask[row] = (tk != 0.f) ? 1.f : 0.f;
    }
}

// ============================================================
// C = relu(A @ W + b)  ; A: [M, 512], W: [512, 512]
// tile 64x64, BK=16, 256 threads, 4x4 micro-tile
// which: 0->g_Q, 1->g_K, 2->g_V
// ============================================================
__global__ void __launch_bounds__(256)
gemm_relu_kernel(const float* __restrict__ A, const float* __restrict__ W,
                 const float* __restrict__ bias, int which) {
    float* C = (which == 0) ? g_Q : (which == 1) ? g_K : g_V;
    __shared__ float As[16][SPAD];   // A transposed: As[k][m]
    __shared__ float Ws[16][SPAD];   // W natural:    Ws[k][n]
    int tid = threadIdx.x;
    int tx = tid & 15, ty = tid >> 4;
    int m0 = blockIdx.y * 64, n0 = blockIdx.x * 64;

    float acc[4][4];
    #pragma unroll
    for (int i = 0; i < 4; i++)
        #pragma unroll
        for (int j = 0; j < 4; j++) acc[i][j] = 0.f;

    for (int k0 = 0; k0 < DMODEL; k0 += 16) {
        {   // A tile 64x16 -> transposed
            int r  = tid >> 2;
            int kk = (tid & 3) << 2;
            float4 v = *(const float4*)&A[(size_t)(m0 + r) * DMODEL + k0 + kk];
            As[kk + 0][r] = v.x; As[kk + 1][r] = v.y;
            As[kk + 2][r] = v.z; As[kk + 3][r] = v.w;
        }
        {   // W tile 16x64
            int kk = tid >> 4;
            int n4 = (tid & 15) << 2;
            *(float4*)&Ws[kk][n4] =
                *(const float4*)&W[(size_t)(k0 + kk) * DMODEL + n0 + n4];
        }
        __syncthreads();
        #pragma unroll
        for (int k = 0; k < 16; k++) {
            float4 a = *(const float4*)&As[k][ty << 2];
            float4 b = *(const float4*)&Ws[k][tx << 2];
            float av[4] = {a.x, a.y, a.z, a.w};
            float bv[4] = {b.x, b.y, b.z, b.w};
            #pragma unroll
            for (int i = 0; i < 4; i++)
                #pragma unroll
                for (int j = 0; j < 4; j++)
                    acc[i][j] = fmaf(av[i], bv[j], acc[i][j]);
        }
        __syncthreads();
    }
    #pragma unroll
    for (int i = 0; i < 4; i++) {
        int m = m0 + (ty << 2) + i;
        float4 o;
        int n = n0 + (tx << 2);
        o.x = fmaxf(acc[i][0] + bias[n + 0], 0.f);
        o.y = fmaxf(acc[i][1] + bias[n + 1], 0.f);
        o.z = fmaxf(acc[i][2] + bias[n + 2], 0.f);
        o.w = fmaxf(acc[i][3] + bias[n + 3], 0.f);
        *(float4*)&C[(size_t)m * DMODEL + n] = o;
    }
}

// ============================================================
// flash attention, fp32, BQ=64, BK=64, dh=64
// grid: (SEQ/64, NHEAD*BATCH), block 256
// smem (dynamic): Qt[64][SPAD] | KV[64][SPAD] | St[64][SPAD]
// ============================================================
__global__ void __launch_bounds__(256)
attn_kernel() {
    extern __shared__ float smem[];
    float* Qt = smem;                 // Q transposed: Qt[d][q]  (scaled)
    float* KV = smem + 64 * SPAD;     // K transposed Kt[d][k]; later V natural Vs[k][d]
    float* St = smem + 2 * 64 * SPAD; // S key-major: St[k][q]
    __shared__ float red[4][64];
    __shared__ float m_s[64], l_s[64], alpha_s[64], kmask_s[64];

    int tid = threadIdx.x;
    int tx = tid & 15, ty = tid >> 4;
    int hb = blockIdx.y;          // head*BATCH + b
    int head = hb >> 2;           // /BATCH
    int b = hb & 3;
    int q0 = blockIdx.x * 64;

    const float* Qbase = g_Q + ((size_t)b * SEQ) * DMODEL + head * DHEAD;
    const float* Kbase = g_K + ((size_t)b * SEQ) * DMODEL + head * DHEAD;
    const float* Vbase = g_V + ((size_t)b * SEQ) * DMODEL + head * DHEAD;

    // load Q tile transposed, pre-scaled by 1/sqrt(dh)=0.125
    #pragma unroll
    for (int it = 0; it < 4; it++) {
        int lin = tid + it * 256;
        int r  = lin >> 4;
        int d4 = (lin & 15) << 2;
        float4 v = *(const float4*)&Qbase[(size_t)(q0 + r) * DMODEL + d4];
        Qt[(d4 + 0) * SPAD + r] = v.x * 0.125f;
        Qt[(d4 + 1) * SPAD + r] = v.y * 0.125f;
        Qt[(d4 + 2) * SPAD + r] = v.z * 0.125f;
        Qt[(d4 + 3) * SPAD + r] = v.w * 0.125f;
    }
    if (tid < 64) { m_s[tid] = -3.0e38f; l_s[tid] = 0.f; }

    float acc[4][4];
    #pragma unroll
    for (int i = 0; i < 4; i++)
        #pragma unroll
        for (int j = 0; j < 4; j++) acc[i][j] = 0.f;
    __syncthreads();

    for (int kt = 0; kt < SEQ; kt += 64) {
        // K tile -> transposed Kt[d][key]
        #pragma unroll
        for (int it = 0; it < 4; it++) {
            int lin = tid + it * 256;
            int r  = lin >> 4;
            int d4 = (lin & 15) << 2;
            float4 v = *(const float4*)&Kbase[(size_t)(kt + r) * DMODEL + d4];
            KV[(d4 + 0) * SPAD + r] = v.x;
            KV[(d4 + 1) * SPAD + r] = v.y;
            KV[(d4 + 2) * SPAD + r] = v.z;
            KV[(d4 + 3) * SPAD + r] = v.w;
        }
        if (tid < 64) kmask_s[tid] = g_kmask[b * SEQ + kt + tid];
        __syncthreads();

        // S = (Q/8) @ K^T  -> 4x4 per thread; rows=queries ty*4.., cols=keys tx*4..
        float sacc[4][4];
        #pragma unroll
        for (int i = 0; i < 4; i++)
            #pragma unroll
            for (int j = 0; j < 4; j++) sacc[i][j] = 0.f;
        #pragma unroll 16
        for (int d = 0; d < DHEAD; d++) {
            float4 qa = *(const float4*)(Qt + d * SPAD + (ty << 2));
            float4 kb = *(const float4*)(KV + d * SPAD + (tx << 2));
            float av[4] = {qa.x, qa.y, qa.z, qa.w};
            float bv[4] = {kb.x, kb.y, kb.z, kb.w};
            #pragma unroll
            for (int i = 0; i < 4; i++)
                #pragma unroll
                for (int j = 0; j < 4; j++)
                    sacc[i][j] = fmaf(av[i], bv[j], sacc[i][j]);
        }
        // apply key mask, store key-major
        #pragma unroll
        for (int j = 0; j < 4; j++) {
            int key = (tx << 2) + j;
            float km = kmask_s[key];
            #pragma unroll
            for (int i = 0; i < 4; i++) {
                float v = (km != 0.f) ? sacc[i][j] : NEG_INF_F;
                St[key * SPAD + (ty << 2) + i] = v;
            }
        }
        __syncthreads();   // St ready; Kt no longer needed

        // V tile -> natural Vs[key][d] (overwrites Kt region)
        #pragma unroll
        for (int it = 0; it < 4; it++) {
            int lin = tid + it * 256;
            int r  = lin >> 4;
            int d4 = (lin & 15) << 2;
            *(float4*)(KV + r * SPAD + d4) =
                *(const float4*)&Vbase[(size_t)(kt + r) * DMODEL + d4];
        }
        // row-max partials (4 chunks x 64 rows)
        {
            int row = tid & 63, ch = tid >> 6;
            float mx = -3.0e38f;
            #pragma unroll
            for (int k = 0; k < 16; k++)
                mx = fmaxf(mx, St[(ch * 16 + k) * SPAD + row]);
            red[ch][row] = mx;
        }
        __syncthreads();
        if (tid < 64) {
            float mo = m_s[tid];
            float mt = fmaxf(fmaxf(red[0][tid], red[1][tid]),
                             fmaxf(red[2][tid], red[3][tid]));
            float mn = fmaxf(mo, mt);
            alpha_s[tid] = __expf(mo - mn);
            m_s[tid] = mn;
        }
        __syncthreads();
        // exp in place + partial row sums
        {
            int row = tid & 63, ch = tid >> 6;
            float mrow = m_s[row];
            float sum = 0.f;
            #pragma unroll
            for (int k = 0; k < 16; k++) {
                int kk = ch * 16 + k;
                float e = __expf(St[kk * SPAD + row] - mrow);
                St[kk * SPAD + row] = e;
                sum += e;
            }
            red[ch][row] = sum;
        }
        __syncthreads();
        if (tid < 64)
            l_s[tid] = l_s[tid] * alpha_s[tid]
                     + red[0][tid] + red[1][tid] + red[2][tid] + red[3][tid];
        // rescale running O
        #pragma unroll
        for (int i = 0; i < 4; i++) {
            float a = alpha_s[(ty << 2) + i];
            #pragma unroll
            for (int j = 0; j < 4; j++) acc[i][j] *= a;
        }
        // O += P @ V
        #pragma unroll 16
        for (int k = 0; k < 64; k++) {
            float4 p  = *(const float4*)(St + k * SPAD + (ty << 2));
            float4 vv = *(const float4*)(KV + k * SPAD + (tx << 2));
            float pv[4] = {p.x, p.y, p.z, p.w};
            float vvv[4] = {vv.x, vv.y, vv.z, vv.w};
            #pragma unroll
            for (int i = 0; i < 4; i++)
                #pragma unroll
                for (int j = 0; j < 4; j++)
                    acc[i][j] = fmaf(pv[i], vvv[j], acc[i][j]);
        }
        __syncthreads();   // guards l_s read below + KV/St reuse next tile
    }

    float* Obase = g_att + ((size_t)(b * SEQ + q0)) * DMODEL + head * DHEAD;
    #pragma unroll
    for (int i = 0; i < 4; i++) {
        int row = (ty << 2) + i;
        float sc = g_qmask[b * SEQ + q0 + row] / l_s[row];
        float4 o;
        o.x = acc[i][0] * sc; o.y = acc[i][1] * sc;
        o.z = acc[i][2] * sc; o.w = acc[i][3] * sc;
        *(float4*)&Obase[(size_t)row * DMODEL + (tx << 2)] = o;
    }
}

// ============================================================
// residual + LayerNorm (unbiased std, eps added to std)
// ============================================================
__global__ void ln_kernel(const float* __restrict__ queries,
                          const float* __restrict__ gamma,
                          const float* __restrict__ beta,
                          float* __restrict__ out) {
    int row = blockIdx.x;
    int tid = threadIdx.x; // 128
    __shared__ float xs[DMODEL];
    __shared__ float rbuf[4];
    __shared__ float s_mean, s_rstd;
    const float* att = g_att + (size_t)row * DMODEL;
    const float* q   = queries + (size_t)row * DMODEL;

    float s = 0.f;
    for (int i = tid; i < DMODEL; i += 128) {
        float v = att[i] + q[i];
        xs[i] = v;
        s += v;
    }
    #pragma unroll
    for (int off = 16; off; off >>= 1) s += __shfl_xor_sync(0xffffffffu, s, off);
    if ((tid & 31) == 0) rbuf[tid >> 5] = s;
    __syncthreads();
    if (tid == 0) s_mean = (rbuf[0] + rbuf[1] + rbuf[2] + rbuf[3]) * (1.0f / DMODEL);
    __syncthreads();
    float mean = s_mean;
    float v2 = 0.f;
    for (int i = tid; i < DMODEL; i += 128) { float d = xs[i] - mean; v2 += d * d; }
    #pragma unroll
    for (int off = 16; off; off >>= 1) v2 += __shfl_xor_sync(0xffffffffu, v2, off);
    if ((tid & 31) == 0) rbuf[tid >> 5] = v2;
    __syncthreads();
    if (tid == 0) {
        float var = (rbuf[0] + rbuf[1] + rbuf[2] + rbuf[3]) * (1.0f / (DMODEL - 1));
        s_rstd = 1.0f / (sqrtf(var) + LN_EPS_F);
    }
    __syncthreads();
    float rstd = s_rstd;
    for (int i = tid; i < DMODEL; i += 128)
        out[(size_t)row * DMODEL + i] = gamma[i] * (xs[i] - mean) * rstd + beta[i];
}

// ============================================================
extern "C" void kernel_launch(void* const* d_in, const int* in_sizes, int n_in,
                              void* d_out, int out_size) {
    const float* queries = (const float*)d_in[0];
    const float* keys    = (const float*)d_in[1];
    const float* values  = (const float*)d_in[2];
    const float* Wq = (const float*)d_in[3];
    const float* bq = (const float*)d_in[4];
    const float* Wk = (const float*)d_in[5];
    const float* bk = (const float*)d_in[6];
    const float* Wv = (const float*)d_in[7];
    const float* bv = (const float*)d_in[8];
    const float* gamma = (const float*)d_in[9];
    const float* beta  = (const float*)d_in[10];
    float* out = (float*)d_out;

    mask_kernel<<<MROWS, 128>>>(queries, keys);

    dim3 ggrid(DMODEL / 64, MROWS / 64);
    gemm_relu_kernel<<<ggrid, 256>>>(queries, Wq, bq, 0);
    gemm_relu_kernel<<<ggrid, 256>>>(keys,    Wk, bk, 1);
    gemm_relu_kernel<<<ggrid, 256>>>(values,  Wv, bv, 2);

    const int ATTN_SMEM = 3 * 64 * SPAD * (int)sizeof(float); // 52224 B
    cudaFuncSetAttribute(attn_kernel,
                         cudaFuncAttributeMaxDynamicSharedMemorySize, ATTN_SMEM);
    dim3 agrid(SEQ / 64, NHEAD * BATCH);
    attn_kernel<<<agrid, 256, ATTN_SMEM>>>();

    ln_kernel<<<MROWS, 128>>>(queries, gamma, beta, out);
}

// round 6
// speedup vs baseline: 2.1464x; 2.1464x over previous
#include <cuda_runtime.h>
#include <stdint.h>
#include <math.h>

#define BATCH 4
#define SEQ   2048
#define DMODEL 512
#define NHEAD 8
#define DHEAD 64
#define MROWS (BATCH*SEQ)          // 8192
#define NEG_INF_F (-4294967295.0f) // -2^32+1
#define LN_EPS_F 1e-8f
#define ASPAD 68                   // padded smem row stride (floats)

// ---- scratch (no allocs allowed) ----
__device__ float g_Q[MROWS*DMODEL];
__device__ float g_K[MROWS*DMODEL];
__device__ float g_V[MROWS*DMODEL];
__device__ float g_att[MROWS*DMODEL];
__device__ float g_qmask[MROWS];
__device__ float g_kmask[MROWS];

// fp32 -> tf32 (round to nearest) kept in a float register
__device__ __forceinline__ float to_tf32(float x) {
    uint32_t u;
    asm("cvt.rna.tf32.f32 %0, %1;" : "=r"(u) : "f"(x));
    return __uint_as_float(u);
}

// D += A @ B   (m16n8k8, tf32 in, fp32 accum; A row-major, B col-major)
#define MMA_TF32(d, a, b0, b1)                                              \
    asm volatile(                                                           \
        "mma.sync.aligned.m16n8k8.row.col.f32.tf32.tf32.f32 "               \
        "{%0,%1,%2,%3}, {%4,%5,%6,%7}, {%8,%9}, {%0,%1,%2,%3};"             \
        : "+f"((d)[0]), "+f"((d)[1]), "+f"((d)[2]), "+f"((d)[3])            \
        : "r"((a)[0]), "r"((a)[1]), "r"((a)[2]), "r"((a)[3]),               \
          "r"(b0), "r"(b1))

// ============================================================
// masks: sign(|sum_d x|) per row, for queries and keys
// ============================================================
__global__ void mask_kernel(const float* __restrict__ queries,
                            const float* __restrict__ keys) {
    int row = blockIdx.x;
    int tid = threadIdx.x; // 128
    const float* q = queries + (size_t)row * DMODEL;
    const float* k = keys    + (size_t)row * DMODEL;
    float sq = 0.f, sk = 0.f;
    for (int i = tid; i < DMODEL; i += 128) { sq += q[i]; sk += k[i]; }
    #pragma unroll
    for (int off = 16; off; off >>= 1) {
        sq += __shfl_xor_sync(0xffffffffu, sq, off);
        sk += __shfl_xor_sync(0xffffffffu, sk, off);
    }
    __shared__ float bq[4], bk[4];
    if ((tid & 31) == 0) { bq[tid >> 5] = sq; bk[tid >> 5] = sk; }
    __syncthreads();
    if (tid == 0) {
        float tq = bq[0] + bq[1] + bq[2] + bq[3];
        float tk = bk[0] + bk[1] + bk[2] + bk[3];
        g_qmask[row] = (tq != 0.f) ? 1.f : 0.f;
        g_kmask[row] = (tk != 0.f) ? 1.f : 0.f;
    }
}

// ============================================================
// C = relu(A @ W + b) via tf32 tensor-core mma
// block: 128 threads (4 warps), tile 64(M) x 64(N), K chunks of 64
// warp w -> rows [w*16, w*16+16)
// ============================================================
__global__ void __launch_bounds__(128)
gemm_relu_tc(const float* __restrict__ A, const float* __restrict__ W,
             const float* __restrict__ bias, int which) {
    float* C = (which == 0) ? g_Q : (which == 1) ? g_K : g_V;
    __shared__ float As[64 * ASPAD];   // A natural [m][k]
    __shared__ float Wt[64 * ASPAD];   // W transposed [n][k]

    int tid = threadIdx.x;
    int w = tid >> 5, lane = tid & 31;
    int g = lane >> 2, tg = lane & 3;
    int m0 = blockIdx.y * 64, n0 = blockIdx.x * 64;
    int mw = w * 16;

    float acc[8][4];
    #pragma unroll
    for (int i = 0; i < 8; i++)
        #pragma unroll
        for (int j = 0; j < 4; j++) acc[i][j] = 0.f;

    for (int k0 = 0; k0 < DMODEL; k0 += 64) {
        // stage A natural (tf32)
        #pragma unroll
        for (int it = 0; it < 8; it++) {
            int lin = tid + it * 128;
            int r = lin >> 4, c4 = (lin & 15) << 2;
            float4 v = *(const float4*)&A[(size_t)(m0 + r) * DMODEL + k0 + c4];
            v.x = to_tf32(v.x); v.y = to_tf32(v.y);
            v.z = to_tf32(v.z); v.w = to_tf32(v.w);
            *(float4*)&As[r * ASPAD + c4] = v;
        }
        // stage W transposed: Wt[n][k]
        #pragma unroll
        for (int it = 0; it < 8; it++) {
            int lin = tid + it * 128;
            int kk = lin & 63;
            int n4 = ((lin >> 6)) << 2;
            float4 v = *(const float4*)&W[(size_t)(k0 + kk) * DMODEL + n0 + n4];
            Wt[(n4 + 0) * ASPAD + kk] = to_tf32(v.x);
            Wt[(n4 + 1) * ASPAD + kk] = to_tf32(v.y);
            Wt[(n4 + 2) * ASPAD + kk] = to_tf32(v.z);
            Wt[(n4 + 3) * ASPAD + kk] = to_tf32(v.w);
        }
        __syncthreads();

        const uint32_t* Au = (const uint32_t*)As;
        const uint32_t* Wu = (const uint32_t*)Wt;
        #pragma unroll
        for (int ks = 0; ks < 8; ks++) {
            uint32_t a[4];
            a[0] = Au[(mw + g) * ASPAD + ks * 8 + tg];
            a[1] = Au[(mw + g + 8) * ASPAD + ks * 8 + tg];
            a[2] = Au[(mw + g) * ASPAD + ks * 8 + tg + 4];
            a[3] = Au[(mw + g + 8) * ASPAD + ks * 8 + tg + 4];
            #pragma unroll
            for (int nb = 0; nb < 8; nb++) {
                uint32_t b0 = Wu[(nb * 8 + g) * ASPAD + ks * 8 + tg];
                uint32_t b1 = Wu[(nb * 8 + g) * ASPAD + ks * 8 + tg + 4];
                MMA_TF32(acc[nb], a, b0, b1);
            }
        }
        __syncthreads();
    }

    // epilogue: bias + relu
    int r0 = m0 + mw + g, r1 = r0 + 8;
    #pragma unroll
    for (int nb = 0; nb < 8; nb++) {
        int c = n0 + nb * 8 + 2 * tg;
        float b0 = bias[c], b1 = bias[c + 1];
        float2 o0, o1;
        o0.x = fmaxf(acc[nb][0] + b0, 0.f);
        o0.y = fmaxf(acc[nb][1] + b1, 0.f);
        o1.x = fmaxf(acc[nb][2] + b0, 0.f);
        o1.y = fmaxf(acc[nb][3] + b1, 0.f);
        *(float2*)&C[(size_t)r0 * DMODEL + c] = o0;
        *(float2*)&C[(size_t)r1 * DMODEL + c] = o1;
    }
}

// ============================================================
// flash attention with tf32 tensor-core mma
// BQ=64 (4 warps x 16 rows), BK=64, dh=64
// grid: (SEQ/64, NHEAD*BATCH), block 128
// dyn smem: Ks[64][ASPAD] | Vt[64][ASPAD] | Ps[64][ASPAD] (Ps doubles as Q stage)
// ============================================================
__global__ void __launch_bounds__(128)
attn_tc_kernel() {
    extern __shared__ float smem[];
    float* Ks = smem;                   // K natural [key][d]
    float* Vt = smem + 64 * ASPAD;      // V transposed [d][key]
    float* Ps = smem + 2 * 64 * ASPAD;  // P [q][key] (per-warp-private rows)
    __shared__ float kms[64];

    int tid = threadIdx.x;
    int w = tid >> 5, lane = tid & 31;
    int g = lane >> 2, tg = lane & 3;
    int hb = blockIdx.y;
    int head = hb >> 2, b = hb & 3;
    int q0 = blockIdx.x * 64;
    int mw = w * 16;

    const float* Qb = g_Q + (size_t)b * SEQ * DMODEL + head * DHEAD;
    const float* Kb = g_K + (size_t)b * SEQ * DMODEL + head * DHEAD;
    const float* Vb = g_V + (size_t)b * SEQ * DMODEL + head * DHEAD;

    // ---- stage Q into Ps (scaled by 1/8, tf32), then grab A-fragments ----
    #pragma unroll
    for (int it = 0; it < 8; it++) {
        int lin = tid + it * 128;
        int r = lin >> 4, c4 = (lin & 15) << 2;
        float4 v = *(const float4*)&Qb[(size_t)(q0 + r) * DMODEL + c4];
        v.x = to_tf32(v.x * 0.125f); v.y = to_tf32(v.y * 0.125f);
        v.z = to_tf32(v.z * 0.125f); v.w = to_tf32(v.w * 0.125f);
        *(float4*)&Ps[r * ASPAD + c4] = v;
    }
    __syncthreads();
    uint32_t Qa[8][4];
    {
        const uint32_t* Pu = (const uint32_t*)Ps;
        #pragma unroll
        for (int ks = 0; ks < 8; ks++) {
            Qa[ks][0] = Pu[(mw + g) * ASPAD + ks * 8 + tg];
            Qa[ks][1] = Pu[(mw + g + 8) * ASPAD + ks * 8 + tg];
            Qa[ks][2] = Pu[(mw + g) * ASPAD + ks * 8 + tg + 4];
            Qa[ks][3] = Pu[(mw + g + 8) * ASPAD + ks * 8 + tg + 4];
        }
    }
    __syncthreads();

    float O[8][4];
    #pragma unroll
    for (int i = 0; i < 8; i++)
        #pragma unroll
        for (int j = 0; j < 4; j++) O[i][j] = 0.f;
    float mr0 = -3.0e38f, mr1 = -3.0e38f;
    float lr0 = 0.f, lr1 = 0.f;

    for (int kt = 0; kt < SEQ; kt += 64) {
        // K tile natural (tf32)
        #pragma unroll
        for (int it = 0; it < 8; it++) {
            int lin = tid + it * 128;
            int r = lin >> 4, c4 = (lin & 15) << 2;
            float4 v = *(const float4*)&Kb[(size_t)(kt + r) * DMODEL + c4];
            v.x = to_tf32(v.x); v.y = to_tf32(v.y);
            v.z = to_tf32(v.z); v.w = to_tf32(v.w);
            *(float4*)&Ks[r * ASPAD + c4] = v;
        }
        // V tile transposed: Vt[d][key] (tf32)
        #pragma unroll
        for (int it = 0; it < 8; it++) {
            int lin = tid + it * 128;
            int kk = lin & 63;
            int d4 = (lin >> 6) << 2;
            float4 v = *(const float4*)&Vb[(size_t)(kt + kk) * DMODEL + d4];
            Vt[(d4 + 0) * ASPAD + kk] = to_tf32(v.x);
            Vt[(d4 + 1) * ASPAD + kk] = to_tf32(v.y);
            Vt[(d4 + 2) * ASPAD + kk] = to_tf32(v.z);
            Vt[(d4 + 3) * ASPAD + kk] = to_tf32(v.w);
        }
        if (tid < 64) kms[tid] = g_kmask[b * SEQ + kt + tid];
        __syncthreads();

        // ---- S = (Q/8) @ K^T  (per warp: 16 x 64 in C-fragments) ----
        float Sc[8][4];
        #pragma unroll
        for (int i = 0; i < 8; i++)
            #pragma unroll
            for (int j = 0; j < 4; j++) Sc[i][j] = 0.f;
        {
            const uint32_t* Ku = (const uint32_t*)Ks;
            #pragma unroll
            for (int nb = 0; nb < 8; nb++) {
                #pragma unroll
                for (int ks = 0; ks < 8; ks++) {
                    uint32_t b0 = Ku[(nb * 8 + g) * ASPAD + ks * 8 + tg];
                    uint32_t b1 = Ku[(nb * 8 + g) * ASPAD + ks * 8 + tg + 4];
                    MMA_TF32(Sc[nb], Qa[ks], b0, b1);
                }
            }
        }

        // ---- key mask + running row max ----
        float mx0 = -3.0e38f, mx1 = -3.0e38f;
        #pragma unroll
        for (int nb = 0; nb < 8; nb++) {
            int c = nb * 8 + 2 * tg;
            float km0 = kms[c], km1 = kms[c + 1];
            Sc[nb][0] = (km0 != 0.f) ? Sc[nb][0] : NEG_INF_F;
            Sc[nb][1] = (km1 != 0.f) ? Sc[nb][1] : NEG_INF_F;
            Sc[nb][2] = (km0 != 0.f) ? Sc[nb][2] : NEG_INF_F;
            Sc[nb][3] = (km1 != 0.f) ? Sc[nb][3] : NEG_INF_F;
            mx0 = fmaxf(mx0, fmaxf(Sc[nb][0], Sc[nb][1]));
            mx1 = fmaxf(mx1, fmaxf(Sc[nb][2], Sc[nb][3]));
        }
        #pragma unroll
        for (int off = 1; off <= 2; off <<= 1) {
            mx0 = fmaxf(mx0, __shfl_xor_sync(0xffffffffu, mx0, off));
            mx1 = fmaxf(mx1, __shfl_xor_sync(0xffffffffu, mx1, off));
        }
        float mn0 = fmaxf(mr0, mx0), mn1 = fmaxf(mr1, mx1);
        float al0 = __expf(mr0 - mn0), al1 = __expf(mr1 - mn1);
        mr0 = mn0; mr1 = mn1;

        // ---- P = exp(S - m): row sums + tf32 store to Ps ----
        float s0 = 0.f, s1 = 0.f;
        #pragma unroll
        for (int nb = 0; nb < 8; nb++) {
            float p00 = __expf(Sc[nb][0] - mn0);
            float p01 = __expf(Sc[nb][1] - mn0);
            float p10 = __expf(Sc[nb][2] - mn1);
            float p11 = __expf(Sc[nb][3] - mn1);
            s0 += p00 + p01; s1 += p10 + p11;
            float2 r0v, r1v;
            r0v.x = to_tf32(p00); r0v.y = to_tf32(p01);
            r1v.x = to_tf32(p10); r1v.y = to_tf32(p11);
            *(float2*)&Ps[(mw + g) * ASPAD + nb * 8 + 2 * tg] = r0v;
            *(float2*)&Ps[(mw + g + 8) * ASPAD + nb * 8 + 2 * tg] = r1v;
        }
        #pragma unroll
        for (int off = 1; off <= 2; off <<= 1) {
            s0 += __shfl_xor_sync(0xffffffffu, s0, off);
            s1 += __shfl_xor_sync(0xffffffffu, s1, off);
        }
        lr0 = lr0 * al0 + s0;
        lr1 = lr1 * al1 + s1;
        #pragma unroll
        for (int nb = 0; nb < 8; nb++) {
            O[nb][0] *= al0; O[nb][1] *= al0;
            O[nb][2] *= al1; O[nb][3] *= al1;
        }
        __syncwarp();   // Ps rows are warp-private; make stores visible in-warp

        // ---- O += P @ V ----
        {
            const uint32_t* Pu = (const uint32_t*)Ps;
            const uint32_t* Vu = (const uint32_t*)Vt;
            #pragma unroll
            for (int ks = 0; ks < 8; ks++) {
                uint32_t a[4];
                a[0] = Pu[(mw + g) * ASPAD + ks * 8 + tg];
                a[1] = Pu[(mw + g + 8) * ASPAD + ks * 8 + tg];
                a[2] = Pu[(mw + g) * ASPAD + ks * 8 + tg + 4];
                a[3] = Pu[(mw + g + 8) * ASPAD + ks * 8 + tg + 4];
                #pragma unroll
                for (int nb = 0; nb < 8; nb++) {
                    uint32_t b0 = Vu[(nb * 8 + g) * ASPAD + ks * 8 + tg];
                    uint32_t b1 = Vu[(nb * 8 + g) * ASPAD + ks * 8 + tg + 4];
                    MMA_TF32(O[nb], a, b0, b1);
                }
            }
        }
        __syncthreads();   // all warps done with Ks/Vt before next tile reload
    }

    // ---- epilogue: query mask, 1/l, write ----
    float qm0 = g_qmask[b * SEQ + q0 + mw + g];
    float qm1 = g_qmask[b * SEQ + q0 + mw + g + 8];
    float sc0 = qm0 / lr0, sc1 = qm1 / lr1;
    float* Ob = g_att + (size_t)(b * SEQ + q0) * DMODEL + head * DHEAD;
    int r0 = mw + g, r1 = r0 + 8;
    #pragma unroll
    for (int nb = 0; nb < 8; nb++) {
        int c = nb * 8 + 2 * tg;
        float2 o0, o1;
        o0.x = O[nb][0] * sc0; o0.y = O[nb][1] * sc0;
        o1.x = O[nb][2] * sc1; o1.y = O[nb][3] * sc1;
        *(float2*)&Ob[(size_t)r0 * DMODEL + c] = o0;
        *(float2*)&Ob[(size_t)r1 * DMODEL + c] = o1;
    }
}

// ============================================================
// residual + LayerNorm (unbiased std, eps added to std)
// ============================================================
__global__ void ln_kernel(const float* __restrict__ queries,
                          const float* __restrict__ gamma,
                          const float* __restrict__ beta,
                          float* __restrict__ out) {
    int row = blockIdx.x;
    int tid = threadIdx.x; // 128
    __shared__ float xs[DMODEL];
    __shared__ float rbuf[4];
    __shared__ float s_mean, s_rstd;
    const float* att = g_att + (size_t)row * DMODEL;
    const float* q   = queries + (size_t)row * DMODEL;

    float s = 0.f;
    for (int i = tid; i < DMODEL; i += 128) {
        float v = att[i] + q[i];
        xs[i] = v;
        s += v;
    }
    #pragma unroll
    for (int off = 16; off; off >>= 1) s += __shfl_xor_sync(0xffffffffu, s, off);
    if ((tid & 31) == 0) rbuf[tid >> 5] = s;
    __syncthreads();
    if (tid == 0) s_mean = (rbuf[0] + rbuf[1] + rbuf[2] + rbuf[3]) * (1.0f / DMODEL);
    __syncthreads();
    float mean = s_mean;
    float v2 = 0.f;
    for (int i = tid; i < DMODEL; i += 128) { float d = xs[i] - mean; v2 += d * d; }
    #pragma unroll
    for (int off = 16; off; off >>= 1) v2 += __shfl_xor_sync(0xffffffffu, v2, off);
    if ((tid & 31) == 0) rbuf[tid >> 5] = v2;
    __syncthreads();
    if (tid == 0) {
        float var = (rbuf[0] + rbuf[1] + rbuf[2] + rbuf[3]) * (1.0f / (DMODEL - 1));
        s_rstd = 1.0f / (sqrtf(var) + LN_EPS_F);
    }
    __syncthreads();
    float rstd = s_rstd;
    for (int i = tid; i < DMODEL; i += 128)
        out[(size_t)row * DMODEL + i] = gamma[i] * (xs[i] - mean) * rstd + beta[i];
}

// ============================================================
extern "C" void kernel_launch(void* const* d_in, const int* in_sizes, int n_in,
                              void* d_out, int out_size) {
    const float* queries = (const float*)d_in[0];
    const float* keys    = (const float*)d_in[1];
    const float* values  = (const float*)d_in[2];
    const float* Wq = (const float*)d_in[3];
    const float* bq = (const float*)d_in[4];
    const float* Wk = (const float*)d_in[5];
    const float* bk = (const float*)d_in[6];
    const float* Wv = (const float*)d_in[7];
    const float* bv = (const float*)d_in[8];
    const float* gamma = (const float*)d_in[9];
    const float* beta  = (const float*)d_in[10];
    float* out = (float*)d_out;

    mask_kernel<<<MROWS, 128>>>(queries, keys);

    dim3 ggrid(DMODEL / 64, MROWS / 64);
    gemm_relu_tc<<<ggrid, 128>>>(queries, Wq, bq, 0);
    gemm_relu_tc<<<ggrid, 128>>>(keys,    Wk, bk, 1);
    gemm_relu_tc<<<ggrid, 128>>>(values,  Wv, bv, 2);

    const int ATTN_SMEM = 3 * 64 * ASPAD * (int)sizeof(float); // 52224 B
    cudaFuncSetAttribute(attn_tc_kernel,
                         cudaFuncAttributeMaxDynamicSharedMemorySize, ATTN_SMEM);
    dim3 agrid(SEQ / 64, NHEAD * BATCH);
    attn_tc_kernel<<<agrid, 128, ATTN_SMEM>>>();

    ln_kernel<<<MROWS, 128>>>(queries, gamma, beta, out);
}

// round 7
// speedup vs baseline: 3.3521x; 1.5617x over previous
#include <cuda_runtime.h>
#include <stdint.h>
#include <math.h>

#define BATCH 4
#define SEQ   2048
#define DMODEL 512
#define NHEAD 8
#define DHEAD 64
#define MROWS (BATCH*SEQ)          // 8192
#define NEG_INF_F (-4294967295.0f) // -2^32+1
#define LN_EPS_F 1e-8f
#define PADU 36                    // padded smem row stride (uint32 = bf16x2 units)

// ---- scratch (no allocs allowed) ----
__device__ float g_Q[MROWS*DMODEL];
__device__ float g_K[MROWS*DMODEL];
__device__ float g_V[MROWS*DMODEL];
__device__ float g_att[MROWS*DMODEL];
__device__ float g_qmask[MROWS];
__device__ float g_kmask[MROWS];

// pack two fp32 -> bf16x2 (lo in low half)
__device__ __forceinline__ uint32_t pack_bf16(float lo, float hi) {
    uint32_t r;
    asm("cvt.rn.bf16x2.f32 %0, %1, %2;" : "=r"(r) : "f"(hi), "f"(lo));
    return r;
}

// D += A @ B   (m16n8k16, bf16 in, fp32 accum; A row-major, B col-major)
#define MMA_BF16(d, a, b0, b1)                                              \
    asm volatile(                                                           \
        "mma.sync.aligned.m16n8k16.row.col.f32.bf16.bf16.f32 "              \
        "{%0,%1,%2,%3}, {%4,%5,%6,%7}, {%8,%9}, {%0,%1,%2,%3};"             \
        : "+f"((d)[0]), "+f"((d)[1]), "+f"((d)[2]), "+f"((d)[3])            \
        : "r"((a)[0]), "r"((a)[1]), "r"((a)[2]), "r"((a)[3]),               \
          "r"(b0), "r"(b1))

// ============================================================
// masks: sign(|sum_d x|) per row, for queries and keys
// ============================================================
__global__ void mask_kernel(const float* __restrict__ queries,
                            const float* __restrict__ keys) {
    int row = blockIdx.x;
    int tid = threadIdx.x; // 128
    const float* q = queries + (size_t)row * DMODEL;
    const float* k = keys    + (size_t)row * DMODEL;
    float sq = 0.f, sk = 0.f;
    for (int i = tid; i < DMODEL; i += 128) { sq += q[i]; sk += k[i]; }
    #pragma unroll
    for (int off = 16; off; off >>= 1) {
        sq += __shfl_xor_sync(0xffffffffu, sq, off);
        sk += __shfl_xor_sync(0xffffffffu, sk, off);
    }
    __shared__ float bq[4], bk[4];
    if ((tid & 31) == 0) { bq[tid >> 5] = sq; bk[tid >> 5] = sk; }
    __syncthreads();
    if (tid == 0) {
        float tq = bq[0] + bq[1] + bq[2] + bq[3];
        float tk = bk[0] + bk[1] + bk[2] + bk[3];
        g_qmask[row] = (tq != 0.f) ? 1.f : 0.f;
        g_kmask[row] = (tk != 0.f) ? 1.f : 0.f;
    }
}

// ============================================================
// C = relu(A @ W + b) via bf16 m16n8k16 mma
// block 128 thr (4 warps), tile M=128 x N=64, K chunks of 64
// warp w -> rows [w*32, w*32+32)
// smem: Ap[m][kpair] (128x32+pad), Wp[n][kpair] (64x32+pad)
// ============================================================
__global__ void __launch_bounds__(128)
gemm_relu_bf16(const float* __restrict__ A, const float* __restrict__ W,
               const float* __restrict__ bias, int which) {
    float* C = (which == 0) ? g_Q : (which == 1) ? g_K : g_V;
    __shared__ uint32_t Ap[128 * PADU];   // 18432 B
    __shared__ uint32_t Wp[64 * PADU];    //  9216 B

    int tid = threadIdx.x;
    int w = tid >> 5, lane = tid & 31;
    int g = lane >> 2, tg = lane & 3;
    int m0 = blockIdx.y * 128, n0 = blockIdx.x * 64;
    int mw = w * 32;

    float acc[16][4];   // [mt*8+nb][4]
    #pragma unroll
    for (int i = 0; i < 16; i++)
        #pragma unroll
        for (int j = 0; j < 4; j++) acc[i][j] = 0.f;

    for (int k0 = 0; k0 < DMODEL; k0 += 64) {
        // stage A [m][kpair]
        #pragma unroll
        for (int it = 0; it < 16; it++) {
            int lin = tid + it * 128;
            int r = lin >> 4, c4 = lin & 15;
            float4 v = *(const float4*)&A[(size_t)(m0 + r) * DMODEL + k0 + c4 * 4];
            uint2 p;
            p.x = pack_bf16(v.x, v.y);
            p.y = pack_bf16(v.z, v.w);
            *(uint2*)&Ap[r * PADU + c4 * 2] = p;
        }
        // stage W transposed [n][kpair]
        #pragma unroll
        for (int it = 0; it < 16; it++) {
            int lin = tid + it * 128;
            int n = lin & 63, kp = lin >> 6;
            float lo = W[(size_t)(k0 + 2 * kp) * DMODEL + n0 + n];
            float hi = W[(size_t)(k0 + 2 * kp + 1) * DMODEL + n0 + n];
            Wp[n * PADU + kp] = pack_bf16(lo, hi);
        }
        __syncthreads();

        #pragma unroll
        for (int ks = 0; ks < 4; ks++) {
            int cb = ks * 8 + tg;
            uint32_t a0[4], a1[4];
            a0[0] = Ap[(mw + g) * PADU + cb];
            a0[1] = Ap[(mw + g + 8) * PADU + cb];
            a0[2] = Ap[(mw + g) * PADU + cb + 4];
            a0[3] = Ap[(mw + g + 8) * PADU + cb + 4];
            a1[0] = Ap[(mw + 16 + g) * PADU + cb];
            a1[1] = Ap[(mw + 24 + g) * PADU + cb];
            a1[2] = Ap[(mw + 16 + g) * PADU + cb + 4];
            a1[3] = Ap[(mw + 24 + g) * PADU + cb + 4];
            #pragma unroll
            for (int nb = 0; nb < 8; nb++) {
                uint32_t b0 = Wp[(nb * 8 + g) * PADU + cb];
                uint32_t b1 = Wp[(nb * 8 + g) * PADU + cb + 4];
                MMA_BF16(acc[nb], a0, b0, b1);
                MMA_BF16(acc[8 + nb], a1, b0, b1);
            }
        }
        __syncthreads();
    }

    // epilogue: bias + relu
    #pragma unroll
    for (int mt = 0; mt < 2; mt++) {
        int r0 = m0 + mw + mt * 16 + g;
        int r1 = r0 + 8;
        #pragma unroll
        for (int nb = 0; nb < 8; nb++) {
            int c = n0 + nb * 8 + 2 * tg;
            float b0v = bias[c], b1v = bias[c + 1];
            const float* ac = acc[mt * 8 + nb];
            float2 o0, o1;
            o0.x = fmaxf(ac[0] + b0v, 0.f);
            o0.y = fmaxf(ac[1] + b1v, 0.f);
            o1.x = fmaxf(ac[2] + b0v, 0.f);
            o1.y = fmaxf(ac[3] + b1v, 0.f);
            *(float2*)&C[(size_t)r0 * DMODEL + c] = o0;
            *(float2*)&C[(size_t)r1 * DMODEL + c] = o1;
        }
    }
}

// ============================================================
// flash attention, bf16 m16n8k16 mma, fp32 softmax
// BQ=128 (4 warps x 32 q-rows), BK=64, dh=64
// grid: (SEQ/128, NHEAD*BATCH), block 128
// dyn smem (uint32 units): Kp[64][PADU] | Vp[64][PADU] | Pp[128][PADU]
// Pp doubles as the Q staging buffer before the main loop.
// ============================================================
__global__ void __launch_bounds__(128)
attn_bf16_kernel() {
    extern __shared__ uint32_t sm[];
    uint32_t* Kp = sm;                 // K [key][kpair]
    uint32_t* Vp = sm + 64 * PADU;     // V [d][keypair]
    uint32_t* Pp = sm + 128 * PADU;    // P [q][keypair] (warp-private rows)
    __shared__ float kms[64];

    int tid = threadIdx.x;
    int w = tid >> 5, lane = tid & 31;
    int g = lane >> 2, tg = lane & 3;
    int hb = blockIdx.y;
    int head = hb >> 2, b = hb & 3;
    int q0 = blockIdx.x * 128;
    int mw = w * 32;

    const float* Qb = g_Q + (size_t)b * SEQ * DMODEL + head * DHEAD;
    const float* Kb = g_K + (size_t)b * SEQ * DMODEL + head * DHEAD;
    const float* Vb = g_V + (size_t)b * SEQ * DMODEL + head * DHEAD;

    // ---- stage Q (scaled 1/8) into Pp, pull A-fragments to regs ----
    #pragma unroll
    for (int it = 0; it < 16; it++) {
        int lin = tid + it * 128;
        int r = lin >> 4, c4 = lin & 15;
        float4 v = *(const float4*)&Qb[(size_t)(q0 + r) * DMODEL + c4 * 4];
        uint2 p;
        p.x = pack_bf16(v.x * 0.125f, v.y * 0.125f);
        p.y = pack_bf16(v.z * 0.125f, v.w * 0.125f);
        *(uint2*)&Pp[r * PADU + c4 * 2] = p;
    }
    __syncthreads();
    uint32_t Qa[4][8];  // [ks][mt*4 + j]
    #pragma unroll
    for (int ks = 0; ks < 4; ks++) {
        int cb = ks * 8 + tg;
        Qa[ks][0] = Pp[(mw + g) * PADU + cb];
        Qa[ks][1] = Pp[(mw + g + 8) * PADU + cb];
        Qa[ks][2] = Pp[(mw + g) * PADU + cb + 4];
        Qa[ks][3] = Pp[(mw + g + 8) * PADU + cb + 4];
        Qa[ks][4] = Pp[(mw + 16 + g) * PADU + cb];
        Qa[ks][5] = Pp[(mw + 24 + g) * PADU + cb];
        Qa[ks][6] = Pp[(mw + 16 + g) * PADU + cb + 4];
        Qa[ks][7] = Pp[(mw + 24 + g) * PADU + cb + 4];
    }

    float O[16][4];
    #pragma unroll
    for (int i = 0; i < 16; i++)
        #pragma unroll
        for (int j = 0; j < 4; j++) O[i][j] = 0.f;
    float mr[4] = {-3.0e38f, -3.0e38f, -3.0e38f, -3.0e38f};
    float lr[4] = {0.f, 0.f, 0.f, 0.f};

    for (int kt = 0; kt < SEQ; kt += 64) {
        // stage K [key][kpair]
        #pragma unroll
        for (int it = 0; it < 8; it++) {
            int lin = tid + it * 128;
            int r = lin >> 4, c4 = lin & 15;
            float4 v = *(const float4*)&Kb[(size_t)(kt + r) * DMODEL + c4 * 4];
            uint2 p;
            p.x = pack_bf16(v.x, v.y);
            p.y = pack_bf16(v.z, v.w);
            *(uint2*)&Kp[r * PADU + c4 * 2] = p;
        }
        // stage V transposed [d][keypair]
        #pragma unroll
        for (int it = 0; it < 16; it++) {
            int lin = tid + it * 128;
            int d = lin & 63, kp = lin >> 6;
            float lo = Vb[(size_t)(kt + 2 * kp) * DMODEL + d];
            float hi = Vb[(size_t)(kt + 2 * kp + 1) * DMODEL + d];
            Vp[d * PADU + kp] = pack_bf16(lo, hi);
        }
        if (tid < 64) kms[tid] = g_kmask[b * SEQ + kt + tid];
        __syncthreads();

        // ---- S = (Q/8) @ K^T : per warp 32 x 64 ----
        float Sc[16][4];
        #pragma unroll
        for (int i = 0; i < 16; i++)
            #pragma unroll
            for (int j = 0; j < 4; j++) Sc[i][j] = 0.f;
        #pragma unroll
        for (int ks = 0; ks < 4; ks++) {
            int cb = ks * 8 + tg;
            #pragma unroll
            for (int nb = 0; nb < 8; nb++) {
                uint32_t b0 = Kp[(nb * 8 + g) * PADU + cb];
                uint32_t b1 = Kp[(nb * 8 + g) * PADU + cb + 4];
                MMA_BF16(Sc[nb], (Qa[ks] + 0), b0, b1);
                MMA_BF16(Sc[8 + nb], (Qa[ks] + 4), b0, b1);
            }
        }

        // ---- key mask + running row max (4 rows/lane) ----
        float mx[4] = {-3.0e38f, -3.0e38f, -3.0e38f, -3.0e38f};
        #pragma unroll
        for (int nb = 0; nb < 8; nb++) {
            int c = nb * 8 + 2 * tg;
            float km0 = kms[c], km1 = kms[c + 1];
            #pragma unroll
            for (int mt = 0; mt < 2; mt++) {
                float* S = Sc[mt * 8 + nb];
                S[0] = (km0 != 0.f) ? S[0] : NEG_INF_F;
                S[1] = (km1 != 0.f) ? S[1] : NEG_INF_F;
                S[2] = (km0 != 0.f) ? S[2] : NEG_INF_F;
                S[3] = (km1 != 0.f) ? S[3] : NEG_INF_F;
                mx[2 * mt]     = fmaxf(mx[2 * mt],     fmaxf(S[0], S[1]));
                mx[2 * mt + 1] = fmaxf(mx[2 * mt + 1], fmaxf(S[2], S[3]));
            }
        }
        #pragma unroll
        for (int off = 1; off <= 2; off <<= 1)
            #pragma unroll
            for (int i = 0; i < 4; i++)
                mx[i] = fmaxf(mx[i], __shfl_xor_sync(0xffffffffu, mx[i], off));

        float mn[4], al[4];
        #pragma unroll
        for (int i = 0; i < 4; i++) {
            mn[i] = fmaxf(mr[i], mx[i]);
            al[i] = __expf(mr[i] - mn[i]);
            mr[i] = mn[i];
        }

        // ---- P = exp(S-m): sums + bf16 pack to Pp ----
        float s[4] = {0.f, 0.f, 0.f, 0.f};
        #pragma unroll
        for (int mt = 0; mt < 2; mt++) {
            int r0 = (mw + mt * 16 + g) * PADU;
            int r1 = (mw + mt * 16 + g + 8) * PADU;
            #pragma unroll
            for (int nb = 0; nb < 8; nb++) {
                float* S = Sc[mt * 8 + nb];
                float p0 = __expf(S[0] - mn[2 * mt]);
                float p1 = __expf(S[1] - mn[2 * mt]);
                float p2 = __expf(S[2] - mn[2 * mt + 1]);
                float p3 = __expf(S[3] - mn[2 * mt + 1]);
                s[2 * mt] += p0 + p1;
                s[2 * mt + 1] += p2 + p3;
                Pp[r0 + nb * 4 + tg] = pack_bf16(p0, p1);
                Pp[r1 + nb * 4 + tg] = pack_bf16(p2, p3);
            }
        }
        #pragma unroll
        for (int off = 1; off <= 2; off <<= 1)
            #pragma unroll
            for (int i = 0; i < 4; i++)
                s[i] += __shfl_xor_sync(0xffffffffu, s[i], off);
        #pragma unroll
        for (int i = 0; i < 4; i++) lr[i] = lr[i] * al[i] + s[i];

        // rescale running O
        #pragma unroll
        for (int mt = 0; mt < 2; mt++)
            #pragma unroll
            for (int nb = 0; nb < 8; nb++) {
                float* o = O[mt * 8 + nb];
                o[0] *= al[2 * mt]; o[1] *= al[2 * mt];
                o[2] *= al[2 * mt + 1]; o[3] *= al[2 * mt + 1];
            }
        __syncwarp();   // Pp rows warp-private

        // ---- O += P @ V ----
        #pragma unroll
        for (int ks = 0; ks < 4; ks++) {
            int cb = ks * 8 + tg;
            uint32_t a0[4], a1[4];
            a0[0] = Pp[(mw + g) * PADU + cb];
            a0[1] = Pp[(mw + g + 8) * PADU + cb];
            a0[2] = Pp[(mw + g) * PADU + cb + 4];
            a0[3] = Pp[(mw + g + 8) * PADU + cb + 4];
            a1[0] = Pp[(mw + 16 + g) * PADU + cb];
            a1[1] = Pp[(mw + 24 + g) * PADU + cb];
            a1[2] = Pp[(mw + 16 + g) * PADU + cb + 4];
            a1[3] = Pp[(mw + 24 + g) * PADU + cb + 4];
            #pragma unroll
            for (int nb = 0; nb < 8; nb++) {
                uint32_t b0 = Vp[(nb * 8 + g) * PADU + cb];
                uint32_t b1 = Vp[(nb * 8 + g) * PADU + cb + 4];
                MMA_BF16(O[nb], a0, b0, b1);
                MMA_BF16(O[8 + nb], a1, b0, b1);
            }
        }
        __syncthreads();   // before Kp/Vp/kms reload
    }

    // ---- epilogue: query mask, 1/l, write ----
    float* Ob = g_att + (size_t)(b * SEQ + q0) * DMODEL + head * DHEAD;
    #pragma unroll
    for (int mt = 0; mt < 2; mt++) {
        int r0 = mw + mt * 16 + g;
        int r1 = r0 + 8;
        float sc0 = g_qmask[b * SEQ + q0 + r0] / lr[2 * mt];
        float sc1 = g_qmask[b * SEQ + q0 + r1] / lr[2 * mt + 1];
        #pragma unroll
        for (int nb = 0; nb < 8; nb++) {
            int c = nb * 8 + 2 * tg;
            const float* o = O[mt * 8 + nb];
            float2 o0, o1;
            o0.x = o[0] * sc0; o0.y = o[1] * sc0;
            o1.x = o[2] * sc1; o1.y = o[3] * sc1;
            *(float2*)&Ob[(size_t)r0 * DMODEL + c] = o0;
            *(float2*)&Ob[(size_t)r1 * DMODEL + c] = o1;
        }
    }
}

// ============================================================
// residual + LayerNorm (unbiased std, eps added to std)
// ============================================================
__global__ void ln_kernel(const float* __restrict__ queries,
                          const float* __restrict__ gamma,
                          const float* __restrict__ beta,
                          float* __restrict__ out) {
    int row = blockIdx.x;
    int tid = threadIdx.x; // 128
    __shared__ float xs[DMODEL];
    __shared__ float rbuf[4];
    __shared__ float s_mean, s_rstd;
    const float* att = g_att + (size_t)row * DMODEL;
    const float* q   = queries + (size_t)row * DMODEL;

    float s = 0.f;
    for (int i = tid; i < DMODEL; i += 128) {
        float v = att[i] + q[i];
        xs[i] = v;
        s += v;
    }
    #pragma unroll
    for (int off = 16; off; off >>= 1) s += __shfl_xor_sync(0xffffffffu, s, off);
    if ((tid & 31) == 0) rbuf[tid >> 5] = s;
    __syncthreads();
    if (tid == 0) s_mean = (rbuf[0] + rbuf[1] + rbuf[2] + rbuf[3]) * (1.0f / DMODEL);
    __syncthreads();
    float mean = s_mean;
    float v2 = 0.f;
    for (int i = tid; i < DMODEL; i += 128) { float d = xs[i] - mean; v2 += d * d; }
    #pragma unroll
    for (int off = 16; off; off >>= 1) v2 += __shfl_xor_sync(0xffffffffu, v2, off);
    if ((tid & 31) == 0) rbuf[tid >> 5] = v2;
    __syncthreads();
    if (tid == 0) {
        float var = (rbuf[0] + rbuf[1] + rbuf[2] + rbuf[3]) * (1.0f / (DMODEL - 1));
        s_rstd = 1.0f / (sqrtf(var) + LN_EPS_F);
    }
    __syncthreads();
    float rstd = s_rstd;
    for (int i = tid; i < DMODEL; i += 128)
        out[(size_t)row * DMODEL + i] = gamma[i] * (xs[i] - mean) * rstd + beta[i];
}

// ============================================================
extern "C" void kernel_launch(void* const* d_in, const int* in_sizes, int n_in,
                              void* d_out, int out_size) {
    const float* queries = (const float*)d_in[0];
    const float* keys    = (const float*)d_in[1];
    const float* values  = (const float*)d_in[2];
    const float* Wq = (const float*)d_in[3];
    const float* bq = (const float*)d_in[4];
    const float* Wk = (const float*)d_in[5];
    const float* bk = (const float*)d_in[6];
    const float* Wv = (const float*)d_in[7];
    const float* bv = (const float*)d_in[8];
    const float* gamma = (const float*)d_in[9];
    const float* beta  = (const float*)d_in[10];
    float* out = (float*)d_out;

    mask_kernel<<<MROWS, 128>>>(queries, keys);

    dim3 ggrid(DMODEL / 64, MROWS / 128);
    gemm_relu_bf16<<<ggrid, 128>>>(queries, Wq, bq, 0);
    gemm_relu_bf16<<<ggrid, 128>>>(keys,    Wk, bk, 1);
    gemm_relu_bf16<<<ggrid, 128>>>(values,  Wv, bv, 2);

    const int ATTN_SMEM = 256 * PADU * (int)sizeof(uint32_t); // 36864 B
    cudaFuncSetAttribute(attn_bf16_kernel,
                         cudaFuncAttributeMaxDynamicSharedMemorySize, ATTN_SMEM);
    dim3 agrid(SEQ / 128, NHEAD * BATCH);
    attn_bf16_kernel<<<agrid, 128, ATTN_SMEM>>>();

    ln_kernel<<<MROWS, 128>>>(queries, gamma, beta, out);
}

// round 8
// speedup vs baseline: 4.9343x; 1.4720x over previous
#include <cuda_runtime.h>
#include <stdint.h>
#include <math.h>

#define BATCH 4
#define SEQ   2048
#define DMODEL 512
#define NHEAD 8
#define DHEAD 64
#define MROWS (BATCH*SEQ)          // 8192
#define DKU   (DMODEL/2)           // 256 uints (bf16 pairs) per row
#define NEG_INF_F (-4294967295.0f) // -2^32+1
#define LN_EPS_F 1e-8f
#define UPAD 36                    // padded smem row stride in uint32 (bank-clean)

// ---- scratch (no allocs allowed) ----
__device__ uint32_t g_inb[3u*MROWS*DKU];   // bf16-packed inputs q|k|v
__device__ uint32_t g_Wb[3u*DMODEL*DKU];   // bf16 W transposed [n][kpair], q|k|v
__device__ uint32_t g_Pq[MROWS*DKU];       // projected Q (bf16 pairs)
__device__ uint32_t g_Pk[MROWS*DKU];
__device__ uint32_t g_Pv[MROWS*DKU];
__device__ float    g_att[MROWS*DMODEL];
__device__ float    g_qmask[MROWS];
__device__ float    g_kmask[MROWS];

// pack two fp32 -> bf16x2 (lo in low half)
__device__ __forceinline__ uint32_t pack_bf16(float lo, float hi) {
    uint32_t r;
    asm("cvt.rn.bf16x2.f32 %0, %1, %2;" : "=r"(r) : "f"(hi), "f"(lo));
    return r;
}

// D += A @ B  (m16n8k16 bf16, fp32 accum; A row-major, B col-major)
#define MMA_BF16(d, a, b0, b1)                                              \
    asm volatile(                                                           \
        "mma.sync.aligned.m16n8k16.row.col.f32.bf16.bf16.f32 "              \
        "{%0,%1,%2,%3}, {%4,%5,%6,%7}, {%8,%9}, {%0,%1,%2,%3};"             \
        : "+f"((d)[0]), "+f"((d)[1]), "+f"((d)[2]), "+f"((d)[3])            \
        : "r"((a)[0]), "r"((a)[1]), "r"((a)[2]), "r"((a)[3]),               \
          "r"(b0), "r"(b1))

__device__ __forceinline__ void cp16(uint32_t* s, const uint32_t* g) {
    uint32_t sa = (uint32_t)__cvta_generic_to_shared(s);
    asm volatile("cp.async.ca.shared.global [%0], [%1], 16;" :: "r"(sa), "l"(g));
}
#define CP_COMMIT() asm volatile("cp.async.commit_group;")
#define CP_WAIT1()  asm volatile("cp.async.wait_group 1;")

// ============================================================
// convert inputs fp32 -> bf16 pairs + row masks (fused)
// grid MROWS, block 128
// ============================================================
__global__ void convert_in_kernel(const float* __restrict__ q,
                                  const float* __restrict__ k,
                                  const float* __restrict__ v) {
    int row = blockIdx.x;
    int tid = threadIdx.x;
    size_t off = (size_t)row * DMODEL + tid * 4;
    size_t uoff = (size_t)row * DKU + tid * 2;

    float4 vq = *(const float4*)&q[off];
    float4 vk = *(const float4*)&k[off];
    float4 vv = *(const float4*)&v[off];
    uint2 pq, pk, pv;
    pq.x = pack_bf16(vq.x, vq.y); pq.y = pack_bf16(vq.z, vq.w);
    pk.x = pack_bf16(vk.x, vk.y); pk.y = pack_bf16(vk.z, vk.w);
    pv.x = pack_bf16(vv.x, vv.y); pv.y = pack_bf16(vv.z, vv.w);
    *(uint2*)&g_inb[uoff]                          = pq;
    *(uint2*)&g_inb[(size_t)MROWS * DKU + uoff]    = pk;
    *(uint2*)&g_inb[(size_t)2 * MROWS * DKU + uoff] = pv;

    float sq = vq.x + vq.y + vq.z + vq.w;
    float sk = vk.x + vk.y + vk.z + vk.w;
    #pragma unroll
    for (int o = 16; o; o >>= 1) {
        sq += __shfl_xor_sync(0xffffffffu, sq, o);
        sk += __shfl_xor_sync(0xffffffffu, sk, o);
    }
    __shared__ float bq[4], bk[4];
    if ((tid & 31) == 0) { bq[tid >> 5] = sq; bk[tid >> 5] = sk; }
    __syncthreads();
    if (tid == 0) {
        float tq = bq[0] + bq[1] + bq[2] + bq[3];
        float tk = bk[0] + bk[1] + bk[2] + bk[3];
        g_qmask[row] = (tq != 0.f) ? 1.f : 0.f;
        g_kmask[row] = (tk != 0.f) ? 1.f : 0.f;
    }
}

// ============================================================
// convert W -> transposed bf16 pairs: g_Wb[z][n][kpair]
// grid (8 n-tiles, 8 k-tiles, 3), block 256, tiles 64x64
// ============================================================
__global__ void convert_w_kernel(const float* __restrict__ Wq,
                                 const float* __restrict__ Wk,
                                 const float* __restrict__ Wv) {
    const float* W = (blockIdx.z == 0) ? Wq : (blockIdx.z == 1) ? Wk : Wv;
    __shared__ float T[64][65];   // T[n][k]
    int n0 = blockIdx.x * 64, k0 = blockIdx.y * 64;
    int tid = threadIdx.x;
    #pragma unroll
    for (int it = 0; it < 16; it++) {
        int lin = tid + it * 256;
        int r = lin >> 6, c = lin & 63;           // r=k, c=n
        T[c][r] = W[(size_t)(k0 + r) * DMODEL + n0 + c];
    }
    __syncthreads();
    uint32_t* out = g_Wb + (size_t)blockIdx.z * DMODEL * DKU;
    #pragma unroll
    for (int it = 0; it < 8; it++) {
        int lin = tid + it * 256;
        int n = lin >> 5, kp = lin & 31;
        out[(size_t)(n0 + n) * DKU + (k0 >> 1) + kp] =
            pack_bf16(T[n][2 * kp], T[n][2 * kp + 1]);
    }
}

// ============================================================
// fused projections: C = relu(A @ W + b), bf16 in/out, fp32 accum
// grid (N/128, M/128, 3), block 256 (8 warps, 4m x 2n), K-chunk 64,
// cp.async double-buffered.
// ============================================================
__global__ void __launch_bounds__(256)
gemm_relu_bf16(const float* __restrict__ biasq,
               const float* __restrict__ biask,
               const float* __restrict__ biasv) {
    int z = blockIdx.z;
    const uint32_t* Ab = g_inb + (size_t)z * MROWS * DKU;
    const uint32_t* Wb = g_Wb + (size_t)z * DMODEL * DKU;
    const float* bias = (z == 0) ? biasq : (z == 1) ? biask : biasv;
    uint32_t* C = (z == 0) ? g_Pq : (z == 1) ? g_Pk : g_Pv;

    extern __shared__ uint32_t sm[];
    uint32_t* Abuf = sm;                    // 2 x 128 x UPAD
    uint32_t* Wbuf = sm + 2 * 128 * UPAD;   // 2 x 128 x UPAD

    int tid = threadIdx.x;
    int w = tid >> 5, lane = tid & 31;
    int g = lane >> 2, tg = lane & 3;
    int wm = w >> 1, wn = w & 1;
    int m0 = blockIdx.y * 128, n0 = blockIdx.x * 128;
    int mw = wm * 32;

    float acc[16][4];
    #pragma unroll
    for (int i = 0; i < 16; i++)
        #pragma unroll
        for (int j = 0; j < 4; j++) acc[i][j] = 0.f;

    // stage chunk k0 into buffer buf (A:128x32u, W:128x32u)
    auto stage = [&](int buf, int k0) {
        const uint32_t* Ag = Ab + (size_t)m0 * DKU + (k0 >> 1);
        const uint32_t* Wg = Wb + (size_t)n0 * DKU + (k0 >> 1);
        uint32_t* Ad = Abuf + buf * 128 * UPAD;
        uint32_t* Wd = Wbuf + buf * 128 * UPAD;
        #pragma unroll
        for (int it = 0; it < 4; it++) {
            int lin = tid + it * 256;
            int r = lin >> 3, c = (lin & 7) << 2;
            cp16(Ad + r * UPAD + c, Ag + (size_t)r * DKU + c);
            cp16(Wd + r * UPAD + c, Wg + (size_t)r * DKU + c);
        }
    };

    stage(0, 0);
    CP_COMMIT();

    for (int i = 0; i < 8; i++) {
        if (i + 1 < 8) stage((i + 1) & 1, (i + 1) * 64);
        CP_COMMIT();
        CP_WAIT1();
        __syncthreads();
        const uint32_t* Ap = Abuf + (i & 1) * 128 * UPAD;
        const uint32_t* Wp = Wbuf + (i & 1) * 128 * UPAD;
        #pragma unroll
        for (int ks = 0; ks < 4; ks++) {
            int cb = ks * 8 + tg;
            uint32_t a0[4], a1[4];
            a0[0] = Ap[(mw + g) * UPAD + cb];
            a0[1] = Ap[(mw + g + 8) * UPAD + cb];
            a0[2] = Ap[(mw + g) * UPAD + cb + 4];
            a0[3] = Ap[(mw + g + 8) * UPAD + cb + 4];
            a1[0] = Ap[(mw + 16 + g) * UPAD + cb];
            a1[1] = Ap[(mw + 24 + g) * UPAD + cb];
            a1[2] = Ap[(mw + 16 + g) * UPAD + cb + 4];
            a1[3] = Ap[(mw + 24 + g) * UPAD + cb + 4];
            #pragma unroll
            for (int nb = 0; nb < 8; nb++) {
                uint32_t b0 = Wp[(wn * 64 + nb * 8 + g) * UPAD + cb];
                uint32_t b1 = Wp[(wn * 64 + nb * 8 + g) * UPAD + cb + 4];
                MMA_BF16(acc[nb], a0, b0, b1);
                MMA_BF16(acc[8 + nb], a1, b0, b1);
            }
        }
        __syncthreads();
    }

    // epilogue: bias + relu -> bf16 pairs
    #pragma unroll
    for (int mt = 0; mt < 2; mt++) {
        int r0 = m0 + mw + mt * 16 + g;
        int r1 = r0 + 8;
        #pragma unroll
        for (int nb = 0; nb < 8; nb++) {
            int c = n0 + wn * 64 + nb * 8 + 2 * tg;
            float b0v = bias[c], b1v = bias[c + 1];
            const float* ac = acc[mt * 8 + nb];
            uint32_t cu = (size_t)0 + (c >> 1);
            C[(size_t)r0 * DKU + cu] =
                pack_bf16(fmaxf(ac[0] + b0v, 0.f), fmaxf(ac[1] + b1v, 0.f));
            C[(size_t)r1 * DKU + cu] =
                pack_bf16(fmaxf(ac[2] + b0v, 0.f), fmaxf(ac[3] + b1v, 0.f));
        }
    }
}

// ============================================================
// flash attention, bf16 m16n8k16 mma, fp32 softmax
// BQ=128 (4 warps x 32 q-rows), BK=64, dh=64
// grid: (SEQ/128, NHEAD*BATCH), block 128
// dyn smem (uint32): Kp[64][UPAD] | Vp[64][UPAD] | Pp[128][UPAD]
// ============================================================
__global__ void __launch_bounds__(128)
attn_bf16_kernel() {
    extern __shared__ uint32_t sm[];
    uint32_t* Kp = sm;                 // K [key][kpair]
    uint32_t* Vp = sm + 64 * UPAD;     // V [d][keypair]
    uint32_t* Pp = sm + 128 * UPAD;    // P [q][keypair] (warp-private rows)
    __shared__ float kms[64];

    int tid = threadIdx.x;
    int w = tid >> 5, lane = tid & 31;
    int g = lane >> 2, tg = lane & 3;
    int hb = blockIdx.y;
    int head = hb >> 2, b = hb & 3;
    int q0 = blockIdx.x * 128;
    int mw = w * 32;
    int hoff = head * 32;   // head offset in uints

    const uint32_t* Qb = g_Pq + (size_t)b * SEQ * DKU + hoff;
    const uint32_t* Kb = g_Pk + (size_t)b * SEQ * DKU + hoff;
    const uint32_t* Vb = g_Pv + (size_t)b * SEQ * DKU + hoff;

    // ---- stage Q (bf16 direct copy) into Pp, pull A-fragments + scale ----
    #pragma unroll
    for (int it = 0; it < 8; it++) {
        int lin = tid + it * 128;
        int r = lin >> 3, c = (lin & 7) << 2;
        *(uint4*)&Pp[r * UPAD + c] = *(const uint4*)&Qb[(size_t)(q0 + r) * DKU + c];
    }
    __syncthreads();
    uint32_t Qa[4][8];
    #pragma unroll
    for (int ks = 0; ks < 4; ks++) {
        int cb = ks * 8 + tg;
        Qa[ks][0] = Pp[(mw + g) * UPAD + cb];
        Qa[ks][1] = Pp[(mw + g + 8) * UPAD + cb];
        Qa[ks][2] = Pp[(mw + g) * UPAD + cb + 4];
        Qa[ks][3] = Pp[(mw + g + 8) * UPAD + cb + 4];
        Qa[ks][4] = Pp[(mw + 16 + g) * UPAD + cb];
        Qa[ks][5] = Pp[(mw + 24 + g) * UPAD + cb];
        Qa[ks][6] = Pp[(mw + 16 + g) * UPAD + cb + 4];
        Qa[ks][7] = Pp[(mw + 24 + g) * UPAD + cb + 4];
    }

    float O[16][4];
    #pragma unroll
    for (int i = 0; i < 16; i++)
        #pragma unroll
        for (int j = 0; j < 4; j++) O[i][j] = 0.f;
    float mr[4] = {-3.0e38f, -3.0e38f, -3.0e38f, -3.0e38f};
    float lr[4] = {0.f, 0.f, 0.f, 0.f};

    for (int kt = 0; kt < SEQ; kt += 64) {
        // stage K (direct uint4 copies)
        #pragma unroll
        for (int it = 0; it < 4; it++) {
            int lin = tid + it * 128;
            int r = lin >> 3, c = (lin & 7) << 2;
            *(uint4*)&Kp[r * UPAD + c] = *(const uint4*)&Kb[(size_t)(kt + r) * DKU + c];
        }
        // stage V transposed [d][keypair] via prmt
        #pragma unroll
        for (int it = 0; it < 16; it++) {
            int lin = tid + it * 128;
            int kp = lin >> 6, d = lin & 63;
            uint32_t a = Vb[(size_t)(kt + 2 * kp) * DKU + (d >> 1)];
            uint32_t bb = Vb[(size_t)(kt + 2 * kp + 1) * DKU + (d >> 1)];
            Vp[d * UPAD + kp] = __byte_perm(a, bb, (d & 1) ? 0x7632 : 0x5410);
        }
        if (tid < 64) kms[tid] = g_kmask[b * SEQ + kt + tid];
        __syncthreads();

        // ---- S = Q @ K^T (scaled later): per warp 32 x 64 ----
        float Sc[16][4];
        #pragma unroll
        for (int i = 0; i < 16; i++)
            #pragma unroll
            for (int j = 0; j < 4; j++) Sc[i][j] = 0.f;
        #pragma unroll
        for (int ks = 0; ks < 4; ks++) {
            int cb = ks * 8 + tg;
            #pragma unroll
            for (int nb = 0; nb < 8; nb++) {
                uint32_t b0 = Kp[(nb * 8 + g) * UPAD + cb];
                uint32_t b1 = Kp[(nb * 8 + g) * UPAD + cb + 4];
                MMA_BF16(Sc[nb], (Qa[ks] + 0), b0, b1);
                MMA_BF16(Sc[8 + nb], (Qa[ks] + 4), b0, b1);
            }
        }
        // scale by 1/sqrt(dh)
        #pragma unroll
        for (int i = 0; i < 16; i++)
            #pragma unroll
            for (int j = 0; j < 4; j++) Sc[i][j] *= 0.125f;

        // ---- key mask + running row max (4 rows/lane) ----
        float mx[4] = {-3.0e38f, -3.0e38f, -3.0e38f, -3.0e38f};
        #pragma unroll
        for (int nb = 0; nb < 8; nb++) {
            int c = nb * 8 + 2 * tg;
            float km0 = kms[c], km1 = kms[c + 1];
            #pragma unroll
            for (int mt = 0; mt < 2; mt++) {
                float* S = Sc[mt * 8 + nb];
                S[0] = (km0 != 0.f) ? S[0] : NEG_INF_F;
                S[1] = (km1 != 0.f) ? S[1] : NEG_INF_F;
                S[2] = (km0 != 0.f) ? S[2] : NEG_INF_F;
                S[3] = (km1 != 0.f) ? S[3] : NEG_INF_F;
                mx[2 * mt]     = fmaxf(mx[2 * mt],     fmaxf(S[0], S[1]));
                mx[2 * mt + 1] = fmaxf(mx[2 * mt + 1], fmaxf(S[2], S[3]));
            }
        }
        #pragma unroll
        for (int off = 1; off <= 2; off <<= 1)
            #pragma unroll
            for (int i = 0; i < 4; i++)
                mx[i] = fmaxf(mx[i], __shfl_xor_sync(0xffffffffu, mx[i], off));

        float mn[4], al[4];
        #pragma unroll
        for (int i = 0; i < 4; i++) {
            mn[i] = fmaxf(mr[i], mx[i]);
            al[i] = __expf(mr[i] - mn[i]);
            mr[i] = mn[i];
        }

        // ---- P = exp(S-m): sums + bf16 pack to Pp ----
        float s[4] = {0.f, 0.f, 0.f, 0.f};
        #pragma unroll
        for (int mt = 0; mt < 2; mt++) {
            int r0 = (mw + mt * 16 + g) * UPAD;
            int r1 = (mw + mt * 16 + g + 8) * UPAD;
            #pragma unroll
            for (int nb = 0; nb < 8; nb++) {
                float* S = Sc[mt * 8 + nb];
                float p0 = __expf(S[0] - mn[2 * mt]);
                float p1 = __expf(S[1] - mn[2 * mt]);
                float p2 = __expf(S[2] - mn[2 * mt + 1]);
                float p3 = __expf(S[3] - mn[2 * mt + 1]);
                s[2 * mt] += p0 + p1;
                s[2 * mt + 1] += p2 + p3;
                Pp[r0 + nb * 4 + tg] = pack_bf16(p0, p1);
                Pp[r1 + nb * 4 + tg] = pack_bf16(p2, p3);
            }
        }
        #pragma unroll
        for (int off = 1; off <= 2; off <<= 1)
            #pragma unroll
            for (int i = 0; i < 4; i++)
                s[i] += __shfl_xor_sync(0xffffffffu, s[i], off);
        #pragma unroll
        for (int i = 0; i < 4; i++) lr[i] = lr[i] * al[i] + s[i];

        // rescale running O
        #pragma unroll
        for (int mt = 0; mt < 2; mt++)
            #pragma unroll
            for (int nb = 0; nb < 8; nb++) {
                float* o = O[mt * 8 + nb];
                o[0] *= al[2 * mt]; o[1] *= al[2 * mt];
                o[2] *= al[2 * mt + 1]; o[3] *= al[2 * mt + 1];
            }
        __syncwarp();   // Pp rows warp-private

        // ---- O += P @ V ----
        #pragma unroll
        for (int ks = 0; ks < 4; ks++) {
            int cb = ks * 8 + tg;
            uint32_t a0[4], a1[4];
            a0[0] = Pp[(mw + g) * UPAD + cb];
            a0[1] = Pp[(mw + g + 8) * UPAD + cb];
            a0[2] = Pp[(mw + g) * UPAD + cb + 4];
            a0[3] = Pp[(mw + g + 8) * UPAD + cb + 4];
            a1[0] = Pp[(mw + 16 + g) * UPAD + cb];
            a1[1] = Pp[(mw + 24 + g) * UPAD + cb];
            a1[2] = Pp[(mw + 16 + g) * UPAD + cb + 4];
            a1[3] = Pp[(mw + 24 + g) * UPAD + cb + 4];
            #pragma unroll
            for (int nb = 0; nb < 8; nb++) {
                uint32_t b0 = Vp[(nb * 8 + g) * UPAD + cb];
                uint32_t b1 = Vp[(nb * 8 + g) * UPAD + cb + 4];
                MMA_BF16(O[nb], a0, b0, b1);
                MMA_BF16(O[8 + nb], a1, b0, b1);
            }
        }
        __syncthreads();   // before Kp/Vp/kms reload
    }

    // ---- epilogue: query mask, 1/l, write fp32 ----
    float* Ob = g_att + (size_t)(b * SEQ + q0) * DMODEL + head * DHEAD;
    #pragma unroll
    for (int mt = 0; mt < 2; mt++) {
        int r0 = mw + mt * 16 + g;
        int r1 = r0 + 8;
        float sc0 = g_qmask[b * SEQ + q0 + r0] / lr[2 * mt];
        float sc1 = g_qmask[b * SEQ + q0 + r1] / lr[2 * mt + 1];
        #pragma unroll
        for (int nb = 0; nb < 8; nb++) {
            int c = nb * 8 + 2 * tg;
            const float* o = O[mt * 8 + nb];
            float2 o0, o1;
            o0.x = o[0] * sc0; o0.y = o[1] * sc0;
            o1.x = o[2] * sc1; o1.y = o[3] * sc1;
            *(float2*)&Ob[(size_t)r0 * DMODEL + c] = o0;
            *(float2*)&Ob[(size_t)r1 * DMODEL + c] = o1;
        }
    }
}

// ============================================================
// residual + LayerNorm (unbiased std, eps added to std)
// ============================================================
__global__ void ln_kernel(const float* __restrict__ queries,
                          const float* __restrict__ gamma,
                          const float* __restrict__ beta,
                          float* __restrict__ out) {
    int row = blockIdx.x;
    int tid = threadIdx.x; // 128
    __shared__ float xs[DMODEL];
    __shared__ float rbuf[4];
    __shared__ float s_mean, s_rstd;
    const float* att = g_att + (size_t)row * DMODEL;
    const float* q   = queries + (size_t)row * DMODEL;

    float s = 0.f;
    for (int i = tid; i < DMODEL; i += 128) {
        float v = att[i] + q[i];
        xs[i] = v;
        s += v;
    }
    #pragma unroll
    for (int off = 16; off; off >>= 1) s += __shfl_xor_sync(0xffffffffu, s, off);
    if ((tid & 31) == 0) rbuf[tid >> 5] = s;
    __syncthreads();
    if (tid == 0) s_mean = (rbuf[0] + rbuf[1] + rbuf[2] + rbuf[3]) * (1.0f / DMODEL);
    __syncthreads();
    float mean = s_mean;
    float v2 = 0.f;
    for (int i = tid; i < DMODEL; i += 128) { float d = xs[i] - mean; v2 += d * d; }
    #pragma unroll
    for (int off = 16; off; off >>= 1) v2 += __shfl_xor_sync(0xffffffffu, v2, off);
    if ((tid & 31) == 0) rbuf[tid >> 5] = v2;
    __syncthreads();
    if (tid == 0) {
        float var = (rbuf[0] + rbuf[1] + rbuf[2] + rbuf[3]) * (1.0f / (DMODEL - 1));
        s_rstd = 1.0f / (sqrtf(var) + LN_EPS_F);
    }
    __syncthreads();
    float rstd = s_rstd;
    for (int i = tid; i < DMODEL; i += 128)
        out[(size_t)row * DMODEL + i] = gamma[i] * (xs[i] - mean) * rstd + beta[i];
}

// ============================================================
extern "C" void kernel_launch(void* const* d_in, const int* in_sizes, int n_in,
                              void* d_out, int out_size) {
    const float* queries = (const float*)d_in[0];
    const float* keys    = (const float*)d_in[1];
    const float* values  = (const float*)d_in[2];
    const float* Wq = (const float*)d_in[3];
    const float* bq = (const float*)d_in[4];
    const float* Wk = (const float*)d_in[5];
    const float* bk = (const float*)d_in[6];
    const float* Wv = (const float*)d_in[7];
    const float* bv = (const float*)d_in[8];
    const float* gamma = (const float*)d_in[9];
    const float* beta  = (const float*)d_in[10];
    float* out = (float*)d_out;

    convert_in_kernel<<<MROWS, 128>>>(queries, keys, values);
    convert_w_kernel<<<dim3(8, 8, 3), 256>>>(Wq, Wk, Wv);

    const int GSMEM = 4 * 128 * UPAD * (int)sizeof(uint32_t); // 73728 B
    cudaFuncSetAttribute(gemm_relu_bf16,
                         cudaFuncAttributeMaxDynamicSharedMemorySize, GSMEM);
    gemm_relu_bf16<<<dim3(DMODEL / 128, MROWS / 128, 3), 256, GSMEM>>>(bq, bk, bv);

    const int ASMEM = 256 * UPAD * (int)sizeof(uint32_t); // 36864 B
    cudaFuncSetAttribute(attn_bf16_kernel,
                         cudaFuncAttributeMaxDynamicSharedMemorySize, ASMEM);
    attn_bf16_kernel<<<dim3(SEQ / 128, NHEAD * BATCH), 128, ASMEM>>>();

    ln_kernel<<<MROWS, 128>>>(queries, gamma, beta, out);
}